// round 15
// baseline (speedup 1.0000x reference)
#include <cuda_runtime.h>
#include <cuda_bf16.h>
#include <math_constants.h>

// Problem constants
#define NB 8          // batch
#define NY 180        // RENDER
#define NX 91         // XDIM+1
#define NV 192        // TEMPLATERES
#define SCALE_IN  (32400.0f / 7077888.0f)  // RENDER^2 / TEMPLATERES^3
#define SCALE_OUT (2.0f / 32400.0f)        // 2 (r_k_val) / 180^2 (irfft2 norm)

#define NRB 180                   // kB-role blocks per batch (1 row each)
#define KA_BLOCKS (NB * NX)       // 728
#define KB_BLOCKS (NB * NRB)      // 1440

typedef unsigned long long ull;

// Scratch (device globals; no allocation allowed). Zero-initialized at load;
// counters are returned to zero by the last kB block of each batch, so every
// graph replay starts from the same state.
__device__ float2 g_tmid[NB * NY * NX];    // after column iDFT:  [b][ky][x]
__device__ ull    g_cand[NB * NRB * 4];    // per-row top-4 packed keys
__device__ int    g_cntA[NB];              // kA column completions per batch
__device__ int    g_cntB[NB];              // kB row completions per batch

// ---- packed key helpers: (orderable float bits << 32) | ~index -------------
__device__ __forceinline__ unsigned f2ord(float v) {
    unsigned u = __float_as_uint(v);
    return (u & 0x80000000u) ? ~u : (u | 0x80000000u);
}
__device__ __forceinline__ float ord2f(unsigned ou) {
    unsigned u = (ou & 0x80000000u) ? (ou ^ 0x80000000u) : ~ou;
    return __uint_as_float(u);
}
__device__ __forceinline__ ull kmax(ull a, ull b) { return a > b ? a : b; }
__device__ __forceinline__ ull kmin(ull a, ull b) { return a < b ? a : b; }

// Branch-free merge of two desc-sorted 4-lists -> top-4 (cold path only).
__device__ __forceinline__ void merge4(ull& a0, ull& a1, ull& a2, ull& a3,
                                       ull b0, ull b1, ull b2, ull b3) {
    ull m0 = kmax(a0, b0);
    ull m1 = kmax(kmax(a1, b1), kmin(a0, b0));
    ull m2 = kmax(kmax(a2, b2), kmax(kmin(a0, b1), kmin(a1, b0)));
    ull m3 = kmax(kmax(a3, b3),
                  kmax(kmin(a1, b1), kmax(kmin(a0, b2), kmin(a2, b0))));
    a0 = m0; a1 = m1; a2 = m2; a3 = m3;
}

// complex rotate: w <- w * s
__device__ __forceinline__ void crot(float2& w, float2 s) {
    float tx = w.x * s.x - w.y * s.y;
    float ty = w.x * s.y + w.y * s.x;
    w.x = tx; w.y = ty;
}

// start twiddle e^{i r theta} for r in 0..3 given w1=e^{i theta}, w2=e^{i 2theta}
__device__ __forceinline__ float2 wstart(int r, float2 w1, float2 w2) {
    if (r == 0) return make_float2(1.0f, 0.0f);
    if (r == 1) return w1;
    if (r == 2) return w2;
    return make_float2(w1.x * w2.x - w1.y * w2.y, w1.x * w2.y + w1.y * w2.x);
}

// ---------------------------------------------------------------------------
// FUSED kernel, one launch.
//  Blocks [0, KA_BLOCKS): role A — sample one (b, x) column + iDFT along y
//    (4-way quarter-chains), write g_tmid, then release-signal g_cntA[b].
//  Blocks [KA_BLOCKS, ...): role B — spin-gate on g_cntA[b] == NX, then c2r
//    DFT along x for one (b, ky) row (4-way), REDUX top-4 -> g_cand; the
//    last row-block per batch merges 180*4 keys and writes the output, then
//    resets both counters for the next graph replay.
//  __launch_bounds__(192, 8) guarantees >= 8 blocks/SM -> >= 1184 co-resident
//  blocks; all 728 role-A blocks have bid < 1184, so they are in wave 1 and
//  spinning role-B blocks can never starve them (forward progress safe).
// ---------------------------------------------------------------------------
__global__ __launch_bounds__(192, 8) void k_fused(
    const float* __restrict__ src,
    const float* __restrict__ rot,
    const float* __restrict__ ref,
    float* __restrict__ out)
{
    __shared__ float2 sdata[NY];       // A: column samples; B: row (91 used)
    __shared__ ull    wtop[6][4];
    __shared__ int    s_last;

    int bid = blockIdx.x;
    int t   = threadIdx.x;             // 0..191

    if (bid < KA_BLOCKS) {
        // =================== role A: sample + iDFT along y ===================
        int x = bid % NX;
        int b = bid / NX;

        if (t < NY) {
            int y = t;
            int g = y + 90; if (g >= 180) g -= 180;     // fftshift pre-map
            float gx = (float)x        * (1.0f / 96.0f);
            float gy = (float)(g - 90) * (1.0f / 96.0f);

            const float* R = rot + b * 9;
            float p0 = gx * R[0] + gy * R[3];
            float p1 = gx * R[1] + gy * R[4];
            float p2 = gx * R[2] + gy * R[5];

            float fx = (p0 + 1.0f) * 0.5f * 191.0f;
            float fy = (p1 + 1.0f) * 0.5f * 191.0f;
            float fz = (p2 + 1.0f) * 0.5f * 191.0f;
            float fx0 = floorf(fx), fy0 = floorf(fy), fz0 = floorf(fz);
            float wx = fx - fx0, wy = fy - fy0, wz = fz - fz0;
            int ix = (int)fx0, iy = (int)fy0, iz = (int)fz0;

            int xc0 = min(max(ix, 0), NV - 1),     xc1 = min(max(ix + 1, 0), NV - 1);
            int yc0 = min(max(iy, 0), NV - 1),     yc1 = min(max(iy + 1, 0), NV - 1);
            int zc0 = min(max(iz, 0), NV - 1),     zc1 = min(max(iz + 1, 0), NV - 1);
            float wx0 = (1.0f - wx) * (((unsigned)ix       < NV) ? 1.0f : 0.0f);
            float wx1 =         wx  * (((unsigned)(ix + 1) < NV) ? 1.0f : 0.0f);
            float wy0 = (1.0f - wy) * (((unsigned)iy       < NV) ? 1.0f : 0.0f);
            float wy1 =         wy  * (((unsigned)(iy + 1) < NV) ? 1.0f : 0.0f);
            float wz0 = (1.0f - wz) * (((unsigned)iz       < NV) ? 1.0f : 0.0f);
            float wz1 =         wz  * (((unsigned)(iz + 1) < NV) ? 1.0f : 0.0f);

            const float* vr = src + (size_t)b * 2 * NV * NV * NV;
            const float* vi = vr + (size_t)NV * NV * NV;

            size_t r00 = ((size_t)zc0 * NV + yc0) * NV;
            size_t r01 = ((size_t)zc0 * NV + yc1) * NV;
            size_t r10 = ((size_t)zc1 * NV + yc0) * NV;
            size_t r11 = ((size_t)zc1 * NV + yc1) * NV;

            float w000 = wz0 * wy0 * wx0, w001 = wz0 * wy0 * wx1;
            float w010 = wz0 * wy1 * wx0, w011 = wz0 * wy1 * wx1;
            float w100 = wz1 * wy0 * wx0, w101 = wz1 * wy0 * wx1;
            float w110 = wz1 * wy1 * wx0, w111 = wz1 * wy1 * wx1;

            float a000 = __ldg(vr + r00 + xc0), a001 = __ldg(vr + r00 + xc1);
            float a010 = __ldg(vr + r01 + xc0), a011 = __ldg(vr + r01 + xc1);
            float a100 = __ldg(vr + r10 + xc0), a101 = __ldg(vr + r10 + xc1);
            float a110 = __ldg(vr + r11 + xc0), a111 = __ldg(vr + r11 + xc1);
            float b000 = __ldg(vi + r00 + xc0), b001 = __ldg(vi + r00 + xc1);
            float b010 = __ldg(vi + r01 + xc0), b011 = __ldg(vi + r01 + xc1);
            float b100 = __ldg(vi + r10 + xc0), b101 = __ldg(vi + r10 + xc1);
            float b110 = __ldg(vi + r11 + xc0), b111 = __ldg(vi + r11 + xc1);

            float re = w000 * a000 + w001 * a001 + w010 * a010 + w011 * a011
                     + w100 * a100 + w101 * a101 + w110 * a110 + w111 * a111;
            float im = w000 * b000 + w001 * b001 + w010 * b010 + w011 * b011
                     + w100 * b100 + w101 * b101 + w110 * b110 + w111 * b111;
            re *= SCALE_IN;
            im *= SCALE_IN;

            const float* rp = ref + ((size_t)(b * NY + y) * NX + x) * 2;
            float rr = rp[0], ri = rp[1];
            sdata[t] = make_float2(re * rr + im * ri, im * rr - re * ri);
        }
        __syncthreads();

        // iDFT along y: quarter-chains, 4 lanes per output ky
        int ky = t >> 2;
        int r  = t & 3;
        bool active = (ky < 46);

        float AX = 0, AY = 0, BX = 0, BY = 0;
        if (active) {
            float s1, c1;
            sincospif((float)ky * (1.0f / 90.0f), &s1, &c1);
            float2 w1 = make_float2(c1, s1);
            float2 w2 = make_float2(c1 * c1 - s1 * s1, 2.0f * c1 * s1);
            float2 w4 = make_float2(w2.x * w2.x - w2.y * w2.y, 2.0f * w2.x * w2.y);
            float2 w  = wstart(r, w1, w2);
            for (int y = r; y < NY; y += 4) {
                float2 v = sdata[y];
                AX += v.x * w.x; AY += v.y * w.x;
                BX += v.x * w.y; BY += v.y * w.y;
                crot(w, w4);
            }
        }
        AX += __shfl_xor_sync(0xFFFFFFFFu, AX, 2);
        AY += __shfl_xor_sync(0xFFFFFFFFu, AY, 2);
        BX += __shfl_xor_sync(0xFFFFFFFFu, BX, 2);
        BY += __shfl_xor_sync(0xFFFFFFFFu, BY, 2);
        float oAX = __shfl_xor_sync(0xFFFFFFFFu, AX, 1);
        float oAY = __shfl_xor_sync(0xFFFFFFFFu, AY, 1);
        float oBX = __shfl_xor_sync(0xFFFFFFFFu, BX, 1);
        float oBY = __shfl_xor_sync(0xFFFFFFFFu, BY, 1);

        if (active) {
            bool ev = ((r & 1) == 0);
            float AXe = ev ? AX : oAX, AXo = ev ? oAX : AX;
            float AYe = ev ? AY : oAY, AYo = ev ? oAY : AY;
            float BXe = ev ? BX : oBX, BXo = ev ? oBX : BX;
            float BYe = ev ? BY : oBY, BYo = ev ? oBY : BY;

            float2* base = g_tmid + (size_t)b * NY * NX + x;
            if (r == 0) {
                float SX = AXe + AXo, SY = AYe + AYo, TX = BXe + BXo, TY = BYe + BYo;
                base[(size_t)ky * NX] = make_float2(SX - TY, TX + SY);
            } else if (r == 1) {
                float SX = AXe + AXo, SY = AYe + AYo, TX = BXe + BXo, TY = BYe + BYo;
                base[(size_t)((NY - ky) % NY) * NX] = make_float2(SX + TY, SY - TX);
            } else if (r == 2 && ky != 45) {
                float DX = AXe - AXo, DY = AYe - AYo, EX = BXe - BXo, EY = BYe - BYo;
                base[(size_t)(90 + ky) * NX] = make_float2(DX - EY, EX + DY);
            } else if (r == 3 && ky != 45) {
                float DX = AXe - AXo, DY = AYe - AYo, EX = BXe - BXo, EY = BYe - BYo;
                base[(size_t)(90 - ky) * NX] = make_float2(DX + EY, DY - EX);
            }
        }

        // Release: every thread fences its writes, block syncs, one atomic.
        __threadfence();
        __syncthreads();
        if (t == 0) atomicAdd(&g_cntA[b], 1);
        return;
    }

    // ===================== role B: c2r DFT + top-4 ==========================
    int rid = bid - KA_BLOCKS;
    int ky  = rid % NRB;
    int b   = rid / NRB;

    // Spin-gate: wait until all NX columns of batch b are published.
    if (t == 0) {
        while (atomicAdd(&g_cntA[b], 0) < NX) __nanosleep(64);
    }
    __syncthreads();
    __threadfence();               // acquire side of the counter handshake

    if (t < NX) sdata[t] = g_tmid[(size_t)(b * NY + ky) * NX + t];
    __syncthreads();

    int m = t >> 2;
    int r = t & 3;
    bool active = (m < 46);

    float A = 0, B = 0;
    if (active) {
        float s1, c1;
        sincospif((float)m * (1.0f / 90.0f), &s1, &c1);
        float2 w1 = make_float2(c1, s1);
        float2 w2 = make_float2(c1 * c1 - s1 * s1, 2.0f * c1 * s1);
        float2 w4 = make_float2(w2.x * w2.x - w2.y * w2.y, 2.0f * w2.x * w2.y);
        float2 w;
        int k0;
        if (r == 0)      { w = w4; k0 = 4; }
        else if (r == 1) { w = w1; k0 = 1; }
        else if (r == 2) { w = w2; k0 = 2; }
        else             { w = wstart(3, w1, w2); k0 = 3; }
        for (int k = k0; k < 90; k += 4) {
            float2 cv = sdata[k];
            A += cv.x * w.x; B += cv.y * w.y;
            crot(w, w4);
        }
    }
    A += __shfl_xor_sync(0xFFFFFFFFu, A, 2);
    B += __shfl_xor_sync(0xFFFFFFFFu, B, 2);
    float oA = __shfl_xor_sync(0xFFFFFFFFu, A, 1);
    float oB = __shfl_xor_sync(0xFFFFFFFFu, B, 1);

    unsigned myv = 0, myi = 0xFFFFFFFFu;
    if (active) {
        bool ev = ((r & 1) == 0);
        float Ae = ev ? A : oA, Ao = ev ? oA : A;
        float Be = ev ? B : oB, Bo = ev ? oB : B;
        float base = sdata[0].x + ((m & 1) ? -sdata[90].x : sdata[90].x);

        float val; unsigned gi; bool emit = true;
        unsigned gb = (unsigned)(ky * NY);
        if (r == 0) {
            val = base + 2.0f * ((Ae - Be) + (Ao - Bo));   // r[m]
            gi = gb + (unsigned)m;
        } else if (r == 1) {
            val = base + 2.0f * ((Ae + Be) + (Ao + Bo));   // r[180-m]
            gi = gb + (unsigned)((NY - m) % NY);
            emit = (m != 0);
        } else if (r == 2) {
            val = base + 2.0f * ((Ae - Be) - (Ao - Bo));   // r[90+m]
            gi = gb + (unsigned)(90 + m);
            emit = (m != 45);
        } else {
            val = base + 2.0f * ((Ae + Be) - (Ao + Bo));   // r[90-m]
            gi = gb + (unsigned)(90 - m);
            emit = (m != 0 && m != 45);
        }
        if (emit) { myv = f2ord(val * SCALE_OUT); myi = gi; }
    }

    // warp top-4 via REDUX
    ull wk0, wk1, wk2, wk3;
    {
        unsigned v = myv, idx = myi;
#define TOP_ITER(DST)                                                       \
        {                                                                   \
            unsigned mv = __reduce_max_sync(0xFFFFFFFFu, v);                \
            unsigned ci = (v == mv) ? idx : 0xFFFFFFFFu;                    \
            unsigned mi = __reduce_min_sync(0xFFFFFFFFu, ci);               \
            if (v == mv && idx == mi) { v = 0; idx = 0xFFFFFFFFu; }         \
            DST = ((ull)mv << 32) | (unsigned)(~mi);                        \
        }
        TOP_ITER(wk0) TOP_ITER(wk1) TOP_ITER(wk2) TOP_ITER(wk3)
    }
    int wid = t >> 5, lane = t & 31;
    if (lane == 0) { wtop[wid][0] = wk0; wtop[wid][1] = wk1; wtop[wid][2] = wk2; wtop[wid][3] = wk3; }
    __syncthreads();

    // block top-4: one warp reduces the 24 warp keys
    if (t < 32) {
        unsigned v = 0, idx = 0xFFFFFFFFu;
        if (t < 24) {
            ull kk = (&wtop[0][0])[t];
            v = (unsigned)(kk >> 32);
            idx = ~((unsigned)(kk & 0xFFFFFFFFu));
        }
        ull bk0, bk1, bk2, bk3;
        {
            unsigned vv = v, ii = idx;
#define TOPB_ITER(DST)                                                      \
            {                                                               \
                unsigned mv = __reduce_max_sync(0xFFFFFFFFu, vv);           \
                unsigned ci = (vv == mv) ? ii : 0xFFFFFFFFu;                \
                unsigned mi = __reduce_min_sync(0xFFFFFFFFu, ci);           \
                if (vv == mv && ii == mi) { vv = 0; ii = 0xFFFFFFFFu; }     \
                DST = ((ull)mv << 32) | (unsigned)(~mi);                    \
            }
            TOPB_ITER(bk0) TOPB_ITER(bk1) TOPB_ITER(bk2) TOPB_ITER(bk3)
        }
        if (t == 0) {
            ull* c = g_cand + (size_t)(b * NRB + ky) * 4;
            c[0] = bk0; c[1] = bk1; c[2] = bk2; c[3] = bk3;
            __threadfence();
            int prev = atomicAdd(&g_cntB[b], 1);
            s_last = (prev == NRB - 1);
        }
    }
    __syncthreads();

    // last row-block of this batch: merge all 180*4 = 720 candidates
    if (s_last) {
        __threadfence();           // acquire: make all g_cand writes visible
        const ull* cand = g_cand + (size_t)b * NRB * 4;
        ull c0 = 0, c1 = 0, c2 = 0, c3 = 0;
#pragma unroll
        for (int j = 0; j < 4; j++) {
            int i = t + j * 192;
            ull xk = (i < NRB * 4) ? cand[i] : 0;
            merge4(c0, c1, c2, c3, xk, 0, 0, 0);
        }
#pragma unroll
        for (int s = 16; s > 0; s >>= 1) {
            ull b0 = __shfl_xor_sync(0xFFFFFFFFu, c0, s);
            ull b1 = __shfl_xor_sync(0xFFFFFFFFu, c1, s);
            ull b2 = __shfl_xor_sync(0xFFFFFFFFu, c2, s);
            ull b3 = __shfl_xor_sync(0xFFFFFFFFu, c3, s);
            merge4(c0, c1, c2, c3, b0, b1, b2, b3);
        }
        __syncthreads();           // wtop reuse safe
        if (lane == 0) { wtop[wid][0] = c0; wtop[wid][1] = c1; wtop[wid][2] = c2; wtop[wid][3] = c3; }
        __syncthreads();
        if (t == 0) {
            ull r0 = wtop[0][0], r1 = wtop[0][1], r2 = wtop[0][2], r3 = wtop[0][3];
#pragma unroll
            for (int w = 1; w < 6; w++)
                merge4(r0, r1, r2, r3, wtop[w][0], wtop[w][1], wtop[w][2], wtop[w][3]);
            ull rs[4] = { r0, r1, r2, r3 };
#pragma unroll
            for (int k = 0; k < 4; k++) {
                ull kk = rs[k];
                float v = ord2f((unsigned)(kk >> 32));
                unsigned gi = ~((unsigned)(kk & 0xFFFFFFFFu));
                int mm = (int)(gi % NY);
                int yy = (int)(gi / NY);
                out[b * 4 + k] = v;
                out[32 + (b * 4 + k) * 2 + 0] = (float)(mm - 90);
                out[32 + (b * 4 + k) * 2 + 1] = (float)(yy - 90);
            }
            // Reset counters for the next graph replay. Safe: all role-A and
            // role-B blocks of batch b have already passed their counter use
            // (g_cntB[b] reached NRB implies every gate was satisfied).
            g_cntA[b] = 0;
            g_cntB[b] = 0;
        }
    }
}

// ---------------------------------------------------------------------------
extern "C" void kernel_launch(void* const* d_in, const int* in_sizes, int n_in,
                              void* d_out, int out_size)
{
    // Positional defaults per metadata order: src, rot, ref_fft, gridF
    const float* src = (const float*)d_in[0];   // 8*2*192^3 = 113246208
    const float* rot = (n_in > 1) ? (const float*)d_in[1] : nullptr;  // 72
    const float* ref = (n_in > 2) ? (const float*)d_in[2] : nullptr;  // 262080
    for (int i = 0; i < n_in; i++) {
        switch (in_sizes[i]) {
            case 113246208: src = (const float*)d_in[i]; break;
            case 72:        rot = (const float*)d_in[i]; break;
            case 262080:    ref = (const float*)d_in[i]; break;
            default: break; // gridF unused — recomputed analytically
        }
    }
    float* out = (float*)d_out;

    k_fused<<<KA_BLOCKS + KB_BLOCKS, 192>>>(src, rot, ref, out);
}

// round 16
// speedup vs baseline: 1.0125x; 1.0125x over previous
#include <cuda_runtime.h>
#include <cuda_bf16.h>
#include <math_constants.h>

// Problem constants
#define NB 8          // batch
#define NY 180        // RENDER
#define NX 91         // XDIM+1
#define NV 192        // TEMPLATERES
#define SCALE_IN  (32400.0f / 7077888.0f)  // RENDER^2 / TEMPLATERES^3
#define SCALE_OUT (2.0f / 32400.0f)        // 2 (r_k_val) / 180^2 (irfft2 norm)

#define NRB 180                   // kB-role blocks per batch (1 row each)
#define KA_BLOCKS (NB * NX)       // 728
#define KB_BLOCKS (NB * NRB)      // 1440

typedef unsigned long long ull;

// Scratch (device globals; no allocation allowed). Zero-initialized at load;
// counters are returned to zero by the last kB block of each batch, so every
// graph replay starts from the same state (replays are stream-ordered).
__device__ float2 g_tmid[NB * NY * NX];    // after column iDFT:  [b][ky][x]
__device__ ull    g_cand[NB * NRB * 4];    // per-row top-4 packed keys
__device__ int    g_cntA[NB];              // kA column completions per batch
__device__ int    g_cntB[NB];              // kB row completions per batch

// ---- scoped sync primitives (cheap handshake; no MEMBAR storms) ------------
__device__ __forceinline__ int ld_acquire_gpu(const int* p) {
    int v;
    asm volatile("ld.acquire.gpu.global.s32 %0, [%1];" : "=r"(v) : "l"(p) : "memory");
    return v;
}
__device__ __forceinline__ void red_release_add(int* p, int v) {
    asm volatile("red.release.gpu.global.add.s32 [%0], %1;" :: "l"(p), "r"(v) : "memory");
}
__device__ __forceinline__ int atom_acqrel_add(int* p, int v) {
    int old;
    asm volatile("atom.acq_rel.gpu.global.add.s32 %0, [%1], %2;"
                 : "=r"(old) : "l"(p), "r"(v) : "memory");
    return old;
}

// ---- packed key helpers: (orderable float bits << 32) | ~index -------------
__device__ __forceinline__ unsigned f2ord(float v) {
    unsigned u = __float_as_uint(v);
    return (u & 0x80000000u) ? ~u : (u | 0x80000000u);
}
__device__ __forceinline__ float ord2f(unsigned ou) {
    unsigned u = (ou & 0x80000000u) ? (ou ^ 0x80000000u) : ~ou;
    return __uint_as_float(u);
}
__device__ __forceinline__ ull kmax(ull a, ull b) { return a > b ? a : b; }
__device__ __forceinline__ ull kmin(ull a, ull b) { return a < b ? a : b; }

// Branch-free merge of two desc-sorted 4-lists -> top-4 (cold path only).
__device__ __forceinline__ void merge4(ull& a0, ull& a1, ull& a2, ull& a3,
                                       ull b0, ull b1, ull b2, ull b3) {
    ull m0 = kmax(a0, b0);
    ull m1 = kmax(kmax(a1, b1), kmin(a0, b0));
    ull m2 = kmax(kmax(a2, b2), kmax(kmin(a0, b1), kmin(a1, b0)));
    ull m3 = kmax(kmax(a3, b3),
                  kmax(kmin(a1, b1), kmax(kmin(a0, b2), kmin(a2, b0))));
    a0 = m0; a1 = m1; a2 = m2; a3 = m3;
}

// complex rotate: w <- w * s
__device__ __forceinline__ void crot(float2& w, float2 s) {
    float tx = w.x * s.x - w.y * s.y;
    float ty = w.x * s.y + w.y * s.x;
    w.x = tx; w.y = ty;
}

// start twiddle e^{i r theta} for r in 0..3 given w1=e^{i theta}, w2=e^{i 2theta}
__device__ __forceinline__ float2 wstart(int r, float2 w1, float2 w2) {
    if (r == 0) return make_float2(1.0f, 0.0f);
    if (r == 1) return w1;
    if (r == 2) return w2;
    return make_float2(w1.x * w2.x - w1.y * w2.y, w1.x * w2.y + w1.y * w2.x);
}

// ---------------------------------------------------------------------------
// FUSED kernel, one launch.
//  Blocks [0, KA_BLOCKS): role A — sample one (b, x) column + iDFT along y,
//    write g_tmid, then __syncthreads + ONE red.release add on g_cntA[b].
//  Blocks [KA_BLOCKS, ...): role B — t0 polls g_cntA[b] with ld.acquire +
//    nanosleep backoff until == NX, __syncthreads broadcasts the acquire,
//    then c2r DFT along x for one (b, ky) row, REDUX top-4 -> g_cand; the
//    last row-block per batch (acq_rel election) merges 180*4 keys, writes
//    the output, and resets both counters for the next graph replay.
//  __launch_bounds__(192, 8) guarantees >= 8 blocks/SM -> >= 1184 co-resident
//  blocks; all 728 role-A blocks have bid < 1184 (wave 1), so spinning
//  role-B blocks can never starve them.
// ---------------------------------------------------------------------------
__global__ __launch_bounds__(192, 8) void k_fused(
    const float* __restrict__ src,
    const float* __restrict__ rot,
    const float* __restrict__ ref,
    float* __restrict__ out)
{
    __shared__ float2 sdata[NY];       // A: column samples; B: row (91 used)
    __shared__ ull    wtop[6][4];
    __shared__ int    s_last;

    int bid = blockIdx.x;
    int t   = threadIdx.x;             // 0..191

    if (bid < KA_BLOCKS) {
        // =================== role A: sample + iDFT along y ===================
        int x = bid % NX;
        int b = bid / NX;

        if (t < NY) {
            int y = t;
            int g = y + 90; if (g >= 180) g -= 180;     // fftshift pre-map
            float gx = (float)x        * (1.0f / 96.0f);
            float gy = (float)(g - 90) * (1.0f / 96.0f);

            const float* R = rot + b * 9;
            float p0 = gx * R[0] + gy * R[3];
            float p1 = gx * R[1] + gy * R[4];
            float p2 = gx * R[2] + gy * R[5];

            float fx = (p0 + 1.0f) * 0.5f * 191.0f;
            float fy = (p1 + 1.0f) * 0.5f * 191.0f;
            float fz = (p2 + 1.0f) * 0.5f * 191.0f;
            float fx0 = floorf(fx), fy0 = floorf(fy), fz0 = floorf(fz);
            float wx = fx - fx0, wy = fy - fy0, wz = fz - fz0;
            int ix = (int)fx0, iy = (int)fy0, iz = (int)fz0;

            int xc0 = min(max(ix, 0), NV - 1),     xc1 = min(max(ix + 1, 0), NV - 1);
            int yc0 = min(max(iy, 0), NV - 1),     yc1 = min(max(iy + 1, 0), NV - 1);
            int zc0 = min(max(iz, 0), NV - 1),     zc1 = min(max(iz + 1, 0), NV - 1);
            float wx0 = (1.0f - wx) * (((unsigned)ix       < NV) ? 1.0f : 0.0f);
            float wx1 =         wx  * (((unsigned)(ix + 1) < NV) ? 1.0f : 0.0f);
            float wy0 = (1.0f - wy) * (((unsigned)iy       < NV) ? 1.0f : 0.0f);
            float wy1 =         wy  * (((unsigned)(iy + 1) < NV) ? 1.0f : 0.0f);
            float wz0 = (1.0f - wz) * (((unsigned)iz       < NV) ? 1.0f : 0.0f);
            float wz1 =         wz  * (((unsigned)(iz + 1) < NV) ? 1.0f : 0.0f);

            const float* vr = src + (size_t)b * 2 * NV * NV * NV;
            const float* vi = vr + (size_t)NV * NV * NV;

            size_t r00 = ((size_t)zc0 * NV + yc0) * NV;
            size_t r01 = ((size_t)zc0 * NV + yc1) * NV;
            size_t r10 = ((size_t)zc1 * NV + yc0) * NV;
            size_t r11 = ((size_t)zc1 * NV + yc1) * NV;

            float w000 = wz0 * wy0 * wx0, w001 = wz0 * wy0 * wx1;
            float w010 = wz0 * wy1 * wx0, w011 = wz0 * wy1 * wx1;
            float w100 = wz1 * wy0 * wx0, w101 = wz1 * wy0 * wx1;
            float w110 = wz1 * wy1 * wx0, w111 = wz1 * wy1 * wx1;

            float a000 = __ldg(vr + r00 + xc0), a001 = __ldg(vr + r00 + xc1);
            float a010 = __ldg(vr + r01 + xc0), a011 = __ldg(vr + r01 + xc1);
            float a100 = __ldg(vr + r10 + xc0), a101 = __ldg(vr + r10 + xc1);
            float a110 = __ldg(vr + r11 + xc0), a111 = __ldg(vr + r11 + xc1);
            float b000 = __ldg(vi + r00 + xc0), b001 = __ldg(vi + r00 + xc1);
            float b010 = __ldg(vi + r01 + xc0), b011 = __ldg(vi + r01 + xc1);
            float b100 = __ldg(vi + r10 + xc0), b101 = __ldg(vi + r10 + xc1);
            float b110 = __ldg(vi + r11 + xc0), b111 = __ldg(vi + r11 + xc1);

            float re = w000 * a000 + w001 * a001 + w010 * a010 + w011 * a011
                     + w100 * a100 + w101 * a101 + w110 * a110 + w111 * a111;
            float im = w000 * b000 + w001 * b001 + w010 * b010 + w011 * b011
                     + w100 * b100 + w101 * b101 + w110 * b110 + w111 * b111;
            re *= SCALE_IN;
            im *= SCALE_IN;

            const float* rp = ref + ((size_t)(b * NY + y) * NX + x) * 2;
            float rr = rp[0], ri = rp[1];
            sdata[t] = make_float2(re * rr + im * ri, im * rr - re * ri);
        }
        __syncthreads();

        // iDFT along y: quarter-chains, 4 lanes per output ky
        int ky = t >> 2;
        int r  = t & 3;
        bool active = (ky < 46);

        float AX = 0, AY = 0, BX = 0, BY = 0;
        if (active) {
            float s1, c1;
            sincospif((float)ky * (1.0f / 90.0f), &s1, &c1);
            float2 w1 = make_float2(c1, s1);
            float2 w2 = make_float2(c1 * c1 - s1 * s1, 2.0f * c1 * s1);
            float2 w4 = make_float2(w2.x * w2.x - w2.y * w2.y, 2.0f * w2.x * w2.y);
            float2 w  = wstart(r, w1, w2);
            for (int y = r; y < NY; y += 4) {
                float2 v = sdata[y];
                AX += v.x * w.x; AY += v.y * w.x;
                BX += v.x * w.y; BY += v.y * w.y;
                crot(w, w4);
            }
        }
        AX += __shfl_xor_sync(0xFFFFFFFFu, AX, 2);
        AY += __shfl_xor_sync(0xFFFFFFFFu, AY, 2);
        BX += __shfl_xor_sync(0xFFFFFFFFu, BX, 2);
        BY += __shfl_xor_sync(0xFFFFFFFFu, BY, 2);
        float oAX = __shfl_xor_sync(0xFFFFFFFFu, AX, 1);
        float oAY = __shfl_xor_sync(0xFFFFFFFFu, AY, 1);
        float oBX = __shfl_xor_sync(0xFFFFFFFFu, BX, 1);
        float oBY = __shfl_xor_sync(0xFFFFFFFFu, BY, 1);

        if (active) {
            bool ev = ((r & 1) == 0);
            float AXe = ev ? AX : oAX, AXo = ev ? oAX : AX;
            float AYe = ev ? AY : oAY, AYo = ev ? oAY : AY;
            float BXe = ev ? BX : oBX, BXo = ev ? oBX : BX;
            float BYe = ev ? BY : oBY, BYo = ev ? oBY : BY;

            float2* base = g_tmid + (size_t)b * NY * NX + x;
            if (r == 0) {
                float SX = AXe + AXo, SY = AYe + AYo, TX = BXe + BXo, TY = BYe + BYo;
                base[(size_t)ky * NX] = make_float2(SX - TY, TX + SY);
            } else if (r == 1) {
                float SX = AXe + AXo, SY = AYe + AYo, TX = BXe + BXo, TY = BYe + BYo;
                base[(size_t)((NY - ky) % NY) * NX] = make_float2(SX + TY, SY - TX);
            } else if (r == 2 && ky != 45) {
                float DX = AXe - AXo, DY = AYe - AYo, EX = BXe - BXo, EY = BYe - BYo;
                base[(size_t)(90 + ky) * NX] = make_float2(DX - EY, EX + DY);
            } else if (r == 3 && ky != 45) {
                float DX = AXe - AXo, DY = AYe - AYo, EX = BXe - BXo, EY = BYe - BYo;
                base[(size_t)(90 - ky) * NX] = make_float2(DX + EY, DY - EX);
            }
        }

        // Release: block-wide HB via syncthreads, then ONE release-atomic.
        __syncthreads();
        if (t == 0) red_release_add(&g_cntA[b], 1);
        return;
    }

    // ===================== role B: c2r DFT + top-4 ==========================
    int rid = bid - KA_BLOCKS;
    int ky  = rid % NRB;
    int b   = rid / NRB;

    // Spin-gate: acquire-load polling (no RMW), exponential backoff.
    if (t == 0) {
        int ns = 32;
        while (ld_acquire_gpu(&g_cntA[b]) < NX) {
            __nanosleep(ns);
            if (ns < 2048) ns <<= 1;
        }
    }
    __syncthreads();               // broadcast the acquire to the block

    if (t < NX) sdata[t] = g_tmid[(size_t)(b * NY + ky) * NX + t];
    __syncthreads();

    int m = t >> 2;
    int r = t & 3;
    bool active = (m < 46);

    float A = 0, B = 0;
    if (active) {
        float s1, c1;
        sincospif((float)m * (1.0f / 90.0f), &s1, &c1);
        float2 w1 = make_float2(c1, s1);
        float2 w2 = make_float2(c1 * c1 - s1 * s1, 2.0f * c1 * s1);
        float2 w4 = make_float2(w2.x * w2.x - w2.y * w2.y, 2.0f * w2.x * w2.y);
        float2 w;
        int k0;
        if (r == 0)      { w = w4; k0 = 4; }
        else if (r == 1) { w = w1; k0 = 1; }
        else if (r == 2) { w = w2; k0 = 2; }
        else             { w = wstart(3, w1, w2); k0 = 3; }
        for (int k = k0; k < 90; k += 4) {
            float2 cv = sdata[k];
            A += cv.x * w.x; B += cv.y * w.y;
            crot(w, w4);
        }
    }
    A += __shfl_xor_sync(0xFFFFFFFFu, A, 2);
    B += __shfl_xor_sync(0xFFFFFFFFu, B, 2);
    float oA = __shfl_xor_sync(0xFFFFFFFFu, A, 1);
    float oB = __shfl_xor_sync(0xFFFFFFFFu, B, 1);

    unsigned myv = 0, myi = 0xFFFFFFFFu;
    if (active) {
        bool ev = ((r & 1) == 0);
        float Ae = ev ? A : oA, Ao = ev ? oA : A;
        float Be = ev ? B : oB, Bo = ev ? oB : B;
        float base = sdata[0].x + ((m & 1) ? -sdata[90].x : sdata[90].x);

        float val; unsigned gi; bool emit = true;
        unsigned gb = (unsigned)(ky * NY);
        if (r == 0) {
            val = base + 2.0f * ((Ae - Be) + (Ao - Bo));   // r[m]
            gi = gb + (unsigned)m;
        } else if (r == 1) {
            val = base + 2.0f * ((Ae + Be) + (Ao + Bo));   // r[180-m]
            gi = gb + (unsigned)((NY - m) % NY);
            emit = (m != 0);
        } else if (r == 2) {
            val = base + 2.0f * ((Ae - Be) - (Ao - Bo));   // r[90+m]
            gi = gb + (unsigned)(90 + m);
            emit = (m != 45);
        } else {
            val = base + 2.0f * ((Ae + Be) - (Ao + Bo));   // r[90-m]
            gi = gb + (unsigned)(90 - m);
            emit = (m != 0 && m != 45);
        }
        if (emit) { myv = f2ord(val * SCALE_OUT); myi = gi; }
    }

    // warp top-4 via REDUX
    ull wk0, wk1, wk2, wk3;
    {
        unsigned v = myv, idx = myi;
#define TOP_ITER(DST)                                                       \
        {                                                                   \
            unsigned mv = __reduce_max_sync(0xFFFFFFFFu, v);                \
            unsigned ci = (v == mv) ? idx : 0xFFFFFFFFu;                    \
            unsigned mi = __reduce_min_sync(0xFFFFFFFFu, ci);               \
            if (v == mv && idx == mi) { v = 0; idx = 0xFFFFFFFFu; }         \
            DST = ((ull)mv << 32) | (unsigned)(~mi);                        \
        }
        TOP_ITER(wk0) TOP_ITER(wk1) TOP_ITER(wk2) TOP_ITER(wk3)
    }
    int wid = t >> 5, lane = t & 31;
    if (lane == 0) { wtop[wid][0] = wk0; wtop[wid][1] = wk1; wtop[wid][2] = wk2; wtop[wid][3] = wk3; }
    __syncthreads();

    // block top-4: one warp reduces the 24 warp keys
    if (t < 32) {
        unsigned v = 0, idx = 0xFFFFFFFFu;
        if (t < 24) {
            ull kk = (&wtop[0][0])[t];
            v = (unsigned)(kk >> 32);
            idx = ~((unsigned)(kk & 0xFFFFFFFFu));
        }
        ull bk0, bk1, bk2, bk3;
        {
            unsigned vv = v, ii = idx;
#define TOPB_ITER(DST)                                                      \
            {                                                               \
                unsigned mv = __reduce_max_sync(0xFFFFFFFFu, vv);           \
                unsigned ci = (vv == mv) ? ii : 0xFFFFFFFFu;                \
                unsigned mi = __reduce_min_sync(0xFFFFFFFFu, ci);           \
                if (vv == mv && ii == mi) { vv = 0; ii = 0xFFFFFFFFu; }     \
                DST = ((ull)mv << 32) | (unsigned)(~mi);                    \
            }
            TOPB_ITER(bk0) TOPB_ITER(bk1) TOPB_ITER(bk2) TOPB_ITER(bk3)
        }
        if (t == 0) {
            ull* c = g_cand + (size_t)(b * NRB + ky) * 4;
            c[0] = bk0; c[1] = bk1; c[2] = bk2; c[3] = bk3;
            // acq_rel: releases this thread's g_cand writes; acquires others'.
            int prev = atom_acqrel_add(&g_cntB[b], 1);
            s_last = (prev == NRB - 1);
        }
    }
    __syncthreads();

    // last row-block of this batch: merge all 180*4 = 720 candidates
    if (s_last) {
        const ull* cand = g_cand + (size_t)b * NRB * 4;
        ull c0 = 0, c1 = 0, c2 = 0, c3 = 0;
#pragma unroll
        for (int j = 0; j < 4; j++) {
            int i = t + j * 192;
            ull xk = (i < NRB * 4) ? cand[i] : 0;
            merge4(c0, c1, c2, c3, xk, 0, 0, 0);
        }
#pragma unroll
        for (int s = 16; s > 0; s >>= 1) {
            ull b0 = __shfl_xor_sync(0xFFFFFFFFu, c0, s);
            ull b1 = __shfl_xor_sync(0xFFFFFFFFu, c1, s);
            ull b2 = __shfl_xor_sync(0xFFFFFFFFu, c2, s);
            ull b3 = __shfl_xor_sync(0xFFFFFFFFu, c3, s);
            merge4(c0, c1, c2, c3, b0, b1, b2, b3);
        }
        __syncthreads();           // wtop reuse safe
        if (lane == 0) { wtop[wid][0] = c0; wtop[wid][1] = c1; wtop[wid][2] = c2; wtop[wid][3] = c3; }
        __syncthreads();
        if (t == 0) {
            ull r0 = wtop[0][0], r1 = wtop[0][1], r2 = wtop[0][2], r3 = wtop[0][3];
#pragma unroll
            for (int w = 1; w < 6; w++)
                merge4(r0, r1, r2, r3, wtop[w][0], wtop[w][1], wtop[w][2], wtop[w][3]);
            ull rs[4] = { r0, r1, r2, r3 };
#pragma unroll
            for (int k = 0; k < 4; k++) {
                ull kk = rs[k];
                float v = ord2f((unsigned)(kk >> 32));
                unsigned gi = ~((unsigned)(kk & 0xFFFFFFFFu));
                int mm = (int)(gi % NY);
                int yy = (int)(gi / NY);
                out[b * 4 + k] = v;
                out[32 + (b * 4 + k) * 2 + 0] = (float)(mm - 90);
                out[32 + (b * 4 + k) * 2 + 1] = (float)(yy - 90);
            }
            // Reset counters for the next graph replay (all users done).
            g_cntA[b] = 0;
            g_cntB[b] = 0;
        }
    }
}

// ---------------------------------------------------------------------------
extern "C" void kernel_launch(void* const* d_in, const int* in_sizes, int n_in,
                              void* d_out, int out_size)
{
    // Positional defaults per metadata order: src, rot, ref_fft, gridF
    const float* src = (const float*)d_in[0];   // 8*2*192^3 = 113246208
    const float* rot = (n_in > 1) ? (const float*)d_in[1] : nullptr;  // 72
    const float* ref = (n_in > 2) ? (const float*)d_in[2] : nullptr;  // 262080
    for (int i = 0; i < n_in; i++) {
        switch (in_sizes[i]) {
            case 113246208: src = (const float*)d_in[i]; break;
            case 72:        rot = (const float*)d_in[i]; break;
            case 262080:    ref = (const float*)d_in[i]; break;
            default: break; // gridF unused — recomputed analytically
        }
    }
    float* out = (float*)d_out;

    k_fused<<<KA_BLOCKS + KB_BLOCKS, 192>>>(src, rot, ref, out);
}